// round 1
// baseline (speedup 1.0000x reference)
#include <cuda_runtime.h>
#include <cuda_bf16.h>
#include <math.h>

// Problem constants
#define BB 8
#define NN 96
#define DD 16
#define H0 50
#define H1 50
#define OUTD 64
#define SLOPE 0.05f

// Scratch (allocation-free: __device__ globals)
__device__ float g_A[BB*NN*H0];     // A[b,j,h]   = x_j . Wxi
__device__ float g_P[BB*NN*H0];     // P[b,j,h]   = deg_j*(Bm_j+b1) + sumC_j + sd_jk_j*w_jk
__device__ float g_adjx[BB*NN*DD];  // (adj @ x)[b,j,d]
__device__ float g_deg[BB*NN];
__device__ float g_sdjk[BB*NN];     // sum_k adj[j,k]*dis[j,k]

__device__ __forceinline__ float leaky(float v) { return v >= 0.f ? v : SLOPE * v; }

// ---------------------------------------------------------------------------
// Kernel 1: per-(b,j) precompute. grid = B*N blocks, 96 threads.
// ---------------------------------------------------------------------------
__global__ void __launch_bounds__(96) sgc_k1(
    const float* __restrict__ x, const float* __restrict__ adj,
    const float* __restrict__ W1, const float* __restrict__ b1)
{
    const int bj = blockIdx.x;
    const int b = bj / NN, j = bj % NN;
    const int tid = threadIdx.x;

    __shared__ float xb[NN*17];     // padded rows (17) for bank-conflict-free col access
    __shared__ float adjrow[NN];
    __shared__ float disrow[NN];
    __shared__ float s[DD];         // sum_k adj[j,k]*x[k,d]
    __shared__ float red[2];        // deg_j, sd_jk

    const float* xB = x + b*NN*DD;
    for (int idx = tid; idx < NN*DD; idx += 96)
        xb[(idx/DD)*17 + (idx%DD)] = xB[idx];
    adjrow[tid] = adj[(b*NN + j)*NN + tid];
    __syncthreads();

    // dis row j (thread per k)
    {
        const int k = tid;
        float d2 = 1e-10f;
        #pragma unroll
        for (int d = 0; d < DD; d++) {
            float df = xb[j*17 + d] - xb[k*17 + d];
            d2 += df * df;
        }
        disrow[k] = sqrtf(d2);
    }
    __syncthreads();

    // warp 0: reduce deg and sd_jk
    if (tid < 32) {
        float dg = 0.f, sd = 0.f;
        #pragma unroll
        for (int k = tid; k < NN; k += 32) {
            float a = adjrow[k];
            dg += a;
            sd += a * disrow[k];
        }
        #pragma unroll
        for (int o = 16; o; o >>= 1) {
            dg += __shfl_down_sync(0xffffffffu, dg, o);
            sd += __shfl_down_sync(0xffffffffu, sd, o);
        }
        if (tid == 0) {
            red[0] = dg; red[1] = sd;
            g_deg[bj] = dg; g_sdjk[bj] = sd;
        }
    }
    // warp 1: s[d] = sum_k adj[j,k]*x[k,d]  (adj @ x row j)
    if (tid >= 32 && tid < 32 + DD) {
        const int d = tid - 32;
        float acc = 0.f;
        #pragma unroll 4
        for (int k = 0; k < NN; k++) acc += adjrow[k] * xb[k*17 + d];
        s[d] = acc;
        g_adjx[bj*DD + d] = acc;
    }
    __syncthreads();

    if (tid < H0) {
        const int h = tid;
        float Av = 0.f, Bv = 0.f, Cv = 0.f;
        #pragma unroll
        for (int d = 0; d < DD; d++) {
            const float xv = xb[j*17 + d];
            Av += xv  * W1[d*H0 + h];          // Wxi
            Bv += xv  * W1[(DD + d)*H0 + h];   // Wxj
            Cv += s[d]* W1[(2*DD + d)*H0 + h]; // Wxk  -> sumC
        }
        const float dg = red[0], sd = red[1];
        g_A[bj*H0 + h] = Av;
        g_P[bj*H0 + h] = dg*(Bv + b1[h]) + Cv + sd * W1[(3*DD + 1)*H0 + h]; // w_jk = row 49
    }
}

// ---------------------------------------------------------------------------
// Kernel 2: per-(b,i) fused message + output. grid = B*N blocks, 128 threads.
// ---------------------------------------------------------------------------
__global__ void __launch_bounds__(128) sgc_k2(
    const float* __restrict__ x, const float* __restrict__ adj,
    const float* __restrict__ W1,
    const float* __restrict__ W2, const float* __restrict__ b2,
    const float* __restrict__ W3, const float* __restrict__ b3,
    float* __restrict__ out)
{
    const int bi = blockIdx.x;
    const int b = bi / NN, i = bi % NN;
    const int tid = threadIdx.x;

    __shared__ float xb[NN*17];
    __shared__ float adjS[NN][97];   // staged adj rows for nonzero j's
    __shared__ float adji[NN];
    __shared__ float dis_i[NN];
    __shared__ float sdik[NN];       // sd_ik[i, nz[m]]
    __shared__ float degS[NN];       // deg[nz[m]]
    __shared__ float dijS[NN];       // dis_i[nz[m]]
    __shared__ float tacc[H0];
    __shared__ float m2s[H1];
    __shared__ float A_i[H0];
    __shared__ float adjx_i[DD];
    __shared__ int   nz[NN];
    __shared__ int   wcnt[3];
    __shared__ int   nnzS;
    __shared__ float scal[2];        // deg_i, sdjk_i

    const float* xB = x + b*NN*DD;
    for (int idx = tid; idx < NN*DD; idx += 128)
        xb[(idx/DD)*17 + (idx%DD)] = xB[idx];
    if (tid < NN)              adji[tid]        = adj[(b*NN + i)*NN + tid];
    if (tid < H0)              A_i[tid]         = g_A[bi*H0 + tid];
    if (tid >= 96 && tid < 96+DD) adjx_i[tid-96] = g_adjx[bi*DD + (tid-96)];
    if (tid == 112)            scal[0] = g_deg[bi];
    if (tid == 113)            scal[1] = g_sdjk[bi];
    __syncthreads();

    // dis row i
    if (tid < NN) {
        const int k = tid;
        float d2 = 1e-10f;
        #pragma unroll
        for (int d = 0; d < DD; d++) {
            float df = xb[i*17 + d] - xb[k*17 + d];
            d2 += df * df;
        }
        dis_i[k] = sqrtf(d2);
    }
    // nonzero compaction via ballot (warps 0..2 are fully active for tid<96)
    bool nzb = false; unsigned mk = 0u;
    if (tid < NN) {
        nzb = (adji[tid] != 0.f);
        mk = __ballot_sync(0xffffffffu, nzb);
        if ((tid & 31) == 0) wcnt[tid >> 5] = __popc(mk);
    }
    __syncthreads();
    if (tid < NN && nzb) {
        const int w = tid >> 5, lane = tid & 31;
        int off = 0;
        #pragma unroll
        for (int u = 0; u < 3; u++) if (u < w) off += wcnt[u];
        off += __popc(mk & ((1u << lane) - 1u));
        nz[off] = tid;
    }
    if (tid == 0) nnzS = wcnt[0] + wcnt[1] + wcnt[2];
    __syncthreads();

    const int nnz = nnzS;

    // stage adj rows for nonzero j's (coalesced), plus per-nz scalars
    for (int idx = tid; idx < nnz*NN; idx += 128) {
        const int m = idx / NN, k = idx % NN;
        adjS[m][k] = adj[(b*NN + nz[m])*NN + k];
    }
    if (tid < nnz) {
        degS[tid] = g_deg[b*NN + nz[tid]];
        dijS[tid] = dis_i[nz[tid]];
    }
    __syncthreads();

    // sd_ik[i, nz[m]] = sum_k dis_i[k] * adj[nz[m], k]
    if (tid < nnz) {
        float acc = 0.f;
        #pragma unroll 4
        for (int k = 0; k < NN; k++) acc += dis_i[k] * adjS[tid][k];
        sdik[tid] = acc;
    }
    __syncthreads();

    // t[h] = sum over nonzero j of leaky(S[i,j,h])
    if (tid < H0) {
        const int h = tid;
        const float wij = W1[(3*DD + 0)*H0 + h];   // row 48
        const float wik = W1[(3*DD + 2)*H0 + h];   // row 50
        const float Ah  = A_i[h];
        float acc = 0.f;
        #pragma unroll 2
        for (int m = 0; m < nnz; m++) {
            const int j = nz[m];
            const float Sv = degS[m]*(Ah + dijS[m]*wij)
                           + g_P[(b*NN + j)*H0 + h]
                           + sdik[m]*wik;
            acc += leaky(Sv);
        }
        tacc[h] = acc;
    }
    __syncthreads();

    // m2_sum[h1] = leaky( g . W2[:,h1] + deg_i*b2[h1] )
    // g = [deg_i*x_i (16), adj@x_i (16), sdjk_i (1), t (50)]
    if (tid < H1) {
        const int h1 = tid;
        const float di = scal[0];
        float acc = di * b2[h1];
        #pragma unroll
        for (int d = 0; d < DD; d++) {
            acc += di * xb[i*17 + d] * W2[d*H1 + h1];
            acc += adjx_i[d]         * W2[(DD + d)*H1 + h1];
        }
        acc += scal[1] * W2[(2*DD)*H1 + h1];
        #pragma unroll 5
        for (int h = 0; h < H0; h++)
            acc += tacc[h] * W2[(2*DD + 1 + h)*H1 + h1];
        m2s[h1] = leaky(acc);
    }
    __syncthreads();

    // m1[o] = leaky( [x_i, m2_sum] . W3[:,o] + b3[o] )
    if (tid < OUTD) {
        const int o = tid;
        float acc = b3[o];
        #pragma unroll
        for (int d = 0; d < DD; d++) acc += xb[i*17 + d] * W3[d*OUTD + o];
        #pragma unroll 5
        for (int h = 0; h < H1; h++) acc += m2s[h] * W3[(DD + h)*OUTD + o];
        out[bi*OUTD + o] = leaky(acc);
    }
}

extern "C" void kernel_launch(void* const* d_in, const int* in_sizes, int n_in,
                              void* d_out, int out_size)
{
    const float* x   = (const float*)d_in[0];
    const float* adj = (const float*)d_in[1];
    const float* W1  = (const float*)d_in[2];
    const float* b1  = (const float*)d_in[3];
    const float* W2  = (const float*)d_in[4];
    const float* b2  = (const float*)d_in[5];
    const float* W3  = (const float*)d_in[6];
    const float* b3  = (const float*)d_in[7];
    float* out = (float*)d_out;

    sgc_k1<<<BB*NN, 96>>>(x, adj, W1, b1);
    sgc_k2<<<BB*NN, 128>>>(x, adj, W1, W2, b2, W3, b3, out);
}

// round 2
// speedup vs baseline: 1.5807x; 1.5807x over previous
#include <cuda_runtime.h>
#include <cuda_bf16.h>
#include <math.h>

#define BB 8
#define NN 96
#define DD 16
#define H0 50
#define H1 50
#define OUTD 64
#define SLOPE 0.05f

// Scratch (__device__ globals; allocation-free)
__device__ float g_A[BB*NN*H0];      // A[b,j,h]   = x_j . Wxi
__device__ float g_P[BB*NN*H0];      // P[b,j,h]   = deg_j*(Bm_j+b1) + sumC_j + sd_jk_j*w_jk
__device__ float g_deg[BB*NN];
__device__ float g_base[BB*NN*H1];   // deg_i*b2 + deg_i*(x_i.W2a) + adjx_i.W2b + sdjk_i*W2c
__device__ float g_xw3[BB*NN*OUTD];  // b3 + x_i.W3a

__device__ __forceinline__ float leaky(float v) { return v >= 0.f ? v : SLOPE * v; }

// ---------------------------------------------------------------------------
// Kernel 1: per-(b,j) precompute. grid = B*N, 128 threads.
// ---------------------------------------------------------------------------
__global__ void __launch_bounds__(128) sgc_k1(
    const float* __restrict__ x, const float* __restrict__ adj,
    const float* __restrict__ W1, const float* __restrict__ b1,
    const float* __restrict__ W2, const float* __restrict__ b2,
    const float* __restrict__ W3, const float* __restrict__ b3)
{
    const int bj = blockIdx.x;
    const int b = bj / NN, j = bj % NN;
    const int tid = threadIdx.x;

    __shared__ float xb[NN*17];
    __shared__ float adjrow[NN];
    __shared__ float disrow[NN];
    __shared__ float s[DD];        // adjx row j
    __shared__ float red[2];       // deg_j, sd_jk

    // Phase 1: loads (x via float4)
    const float4* xB4 = (const float4*)(x + b*NN*DD);
    for (int idx = tid; idx < NN*DD/4; idx += 128) {
        float4 v = xB4[idx];
        const int base = (idx >> 2)*17 + (idx & 3)*4;
        xb[base+0] = v.x; xb[base+1] = v.y; xb[base+2] = v.z; xb[base+3] = v.w;
    }
    if (tid < NN) adjrow[tid] = adj[(b*NN + j)*NN + tid];
    __syncthreads();

    // Phase 2: dis row j
    if (tid < NN) {
        float d2 = 1e-10f;
        #pragma unroll
        for (int d = 0; d < DD; d++) {
            const float df = xb[j*17 + d] - xb[tid*17 + d];
            d2 += df * df;
        }
        disrow[tid] = sqrtf(d2);
    }
    __syncthreads();

    // Phase 3: warp0 reduce deg/sd_jk; warp1 adjx; tid>=64 g_xw3
    if (tid < 32) {
        float dg = 0.f, sd = 0.f;
        #pragma unroll
        for (int k = tid; k < NN; k += 32) {
            const float a = adjrow[k];
            dg += a; sd += a * disrow[k];
        }
        #pragma unroll
        for (int o = 16; o; o >>= 1) {
            dg += __shfl_down_sync(0xffffffffu, dg, o);
            sd += __shfl_down_sync(0xffffffffu, sd, o);
        }
        if (tid == 0) { red[0] = dg; red[1] = sd; g_deg[bj] = dg; }
    }
    if (tid >= 32 && tid < 32 + DD) {
        const int d = tid - 32;
        float acc = 0.f;
        #pragma unroll 4
        for (int k = 0; k < NN; k++) acc += adjrow[k] * xb[k*17 + d];
        s[d] = acc;
    }
    if (tid >= 64) {     // g_xw3[o] = b3 + x_j . W3[0:16]
        const int o = tid - 64;
        float acc = b3[o];
        #pragma unroll
        for (int d = 0; d < DD; d++) acc += xb[j*17 + d] * W3[d*OUTD + o];
        g_xw3[bj*OUTD + o] = acc;
    }
    __syncthreads();

    // Phase 4: A/P (tid<50) and g_base (tid in [64,114))
    if (tid < H0) {
        const int h = tid;
        float Av = 0.f, Bv = 0.f, Cv = 0.f;
        #pragma unroll
        for (int d = 0; d < DD; d++) {
            const float xv = xb[j*17 + d];
            Av += xv   * W1[d*H0 + h];
            Bv += xv   * W1[(DD + d)*H0 + h];
            Cv += s[d] * W1[(2*DD + d)*H0 + h];
        }
        g_A[bj*H0 + h] = Av;
        g_P[bj*H0 + h] = red[0]*(Bv + b1[h]) + Cv + red[1] * W1[(3*DD + 1)*H0 + h];
    } else if (tid >= 64 && tid < 64 + H1) {
        const int h1 = tid - 64;
        const float dg = red[0];
        float acc = dg * b2[h1];
        #pragma unroll
        for (int d = 0; d < DD; d++) {
            acc += dg * xb[j*17 + d] * W2[d*H1 + h1];
            acc += s[d]              * W2[(DD + d)*H1 + h1];
        }
        acc += red[1] * W2[(2*DD)*H1 + h1];
        g_base[bj*H1 + h1] = acc;
    }
}

// ---------------------------------------------------------------------------
// Kernel 2: per-(b,i) message + output. grid = B*N, 128 threads.
// ---------------------------------------------------------------------------
__global__ void __launch_bounds__(128) sgc_k2(
    const float* __restrict__ x, const float* __restrict__ adj,
    const float* __restrict__ W1,
    const float* __restrict__ W2,
    const float* __restrict__ W3,
    float* __restrict__ out)
{
    const int bi = blockIdx.x;
    const int b = bi / NN, i = bi % NN;
    const int tid = threadIdx.x;

    __shared__ float xb[NN*17];
    __shared__ float dis_i[NN];
    __shared__ float Pst[NN*H0];     // staged P rows for nz j's (worst case 96)
    __shared__ float sdik[NN];
    __shared__ float ddeg[NN];       // deg_j
    __shared__ float ddij[NN];       // deg_j * dis_ij
    __shared__ float A_i[H0];
    __shared__ float tacc[H0];
    __shared__ float m2s[H1];
    __shared__ int   nz[NN];
    __shared__ int   wcnt[3];
    __shared__ int   nnzS;

    // Phase A: loads
    const float4* xB4 = (const float4*)(x + b*NN*DD);
    for (int idx = tid; idx < NN*DD/4; idx += 128) {
        float4 v = xB4[idx];
        const int base = (idx >> 2)*17 + (idx & 3)*4;
        xb[base+0] = v.x; xb[base+1] = v.y; xb[base+2] = v.z; xb[base+3] = v.w;
    }
    float adjv = 0.f;
    if (tid < NN) adjv = adj[(b*NN + i)*NN + tid];
    if (tid < H0) A_i[tid] = g_A[bi*H0 + tid];
    __syncthreads();

    // Phase B: dis_i + nonzero compaction
    bool nzb = false; unsigned mk = 0u;
    if (tid < NN) {
        float d2 = 1e-10f;
        #pragma unroll
        for (int d = 0; d < DD; d++) {
            const float df = xb[i*17 + d] - xb[tid*17 + d];
            d2 += df * df;
        }
        dis_i[tid] = sqrtf(d2);
        nzb = (adjv != 0.f);
        mk = __ballot_sync(0xffffffffu, nzb);
        if ((tid & 31) == 0) wcnt[tid >> 5] = __popc(mk);
    }
    __syncthreads();
    if (tid < NN && nzb) {
        const int w = tid >> 5, lane = tid & 31;
        int off = __popc(mk & ((1u << lane) - 1u));
        #pragma unroll
        for (int u = 0; u < 3; u++) if (u < w) off += wcnt[u];
        nz[off] = tid;
    }
    if (tid == 0) nnzS = wcnt[0] + wcnt[1] + wcnt[2];
    __syncthreads();

    const int nnz = nnzS;

    // Phase C: stage P rows (all threads), per-m scalars, sd_ik (warp per m)
    for (int idx = tid; idx < nnz*H0; idx += 128) {
        const int m = idx / H0, h = idx % H0;
        Pst[m*H0 + h] = g_P[(b*NN + nz[m])*H0 + h];
    }
    if (tid < nnz) {
        const float dg = g_deg[b*NN + nz[tid]];
        ddeg[tid] = dg;
        ddij[tid] = dg * dis_i[nz[tid]];
    }
    {
        const int w = tid >> 5, lane = tid & 31;
        for (int m = w; m < nnz; m += 4) {
            const float* row = adj + (b*NN + nz[m])*NN;
            float v = row[lane]      * dis_i[lane]
                    + row[lane+32]   * dis_i[lane+32]
                    + row[lane+64]   * dis_i[lane+64];
            #pragma unroll
            for (int o = 16; o; o >>= 1) v += __shfl_down_sync(0xffffffffu, v, o);
            if (lane == 0) sdik[m] = v;
        }
    }
    __syncthreads();

    // Phase D: t[h] = sum over nz j of leaky(S)  — pure smem
    if (tid < H0) {
        const int h = tid;
        const float wij = W1[(3*DD + 0)*H0 + h];
        const float wik = W1[(3*DD + 2)*H0 + h];
        const float Ah  = A_i[h];
        float acc = 0.f;
        #pragma unroll 4
        for (int m = 0; m < nnz; m++) {
            const float Sv = fmaf(ddeg[m], Ah,
                             fmaf(ddij[m], wij,
                             fmaf(sdik[m], wik, Pst[m*H0 + h])));
            acc += leaky(Sv);
        }
        tacc[h] = acc;
    }
    __syncthreads();

    // Phase E: m2_sum = leaky(g_base + t . W2d)
    if (tid < H1) {
        float acc = g_base[bi*H1 + tid];
        #pragma unroll 5
        for (int h = 0; h < H0; h++)
            acc += tacc[h] * W2[(2*DD + 1 + h)*H1 + tid];
        m2s[tid] = leaky(acc);
    }
    __syncthreads();

    // Phase F: out = leaky(g_xw3 + m2s . W3b)
    if (tid < OUTD) {
        float acc = g_xw3[bi*OUTD + tid];
        #pragma unroll 5
        for (int h = 0; h < H1; h++)
            acc += m2s[h] * W3[(DD + h)*OUTD + tid];
        out[bi*OUTD + tid] = leaky(acc);
    }
}

extern "C" void kernel_launch(void* const* d_in, const int* in_sizes, int n_in,
                              void* d_out, int out_size)
{
    const float* x   = (const float*)d_in[0];
    const float* adj = (const float*)d_in[1];
    const float* W1  = (const float*)d_in[2];
    const float* b1  = (const float*)d_in[3];
    const float* W2  = (const float*)d_in[4];
    const float* b2  = (const float*)d_in[5];
    const float* W3  = (const float*)d_in[6];
    const float* b3  = (const float*)d_in[7];
    float* out = (float*)d_out;

    sgc_k1<<<BB*NN, 128>>>(x, adj, W1, b1, W2, b2, W3, b3);
    sgc_k2<<<BB*NN, 128>>>(x, adj, W1, W2, W3, out);
}

// round 3
// speedup vs baseline: 1.9020x; 1.2033x over previous
#include <cuda_runtime.h>
#include <cuda_bf16.h>
#include <math.h>

#define BB 8
#define NN 96
#define DD 16
#define H0 50
#define H1 50
#define OUTD 64
#define SLOPE 0.05f
#define CHUNK 24

// Scratch (__device__ globals; allocation-free)
__device__ float g_A[BB*NN*H0];      // A[b,j,h]   = x_j . Wxi
__device__ float g_P[BB*NN*H0];      // P[b,j,h]
__device__ float g_deg[BB*NN];
__device__ float g_base[BB*NN*H1];   // deg*b2 + deg*(x.W2a) + adjx.W2b + sdjk*W2c
__device__ float g_xw3[BB*NN*OUTD];  // b3 + x.W3a

__device__ __forceinline__ float leaky(float v) { return v >= 0.f ? v : SLOPE * v; }

// ---------------------------------------------------------------------------
// Kernel 1: per-(b,j) precompute. grid = B*N, 128 threads.
// All weight slabs staged to smem up-front (one load epoch), then smem-only.
// ---------------------------------------------------------------------------
__global__ void __launch_bounds__(128) sgc_k1(
    const float* __restrict__ x, const float* __restrict__ adj,
    const float* __restrict__ W1, const float* __restrict__ b1,
    const float* __restrict__ W2, const float* __restrict__ b2,
    const float* __restrict__ W3, const float* __restrict__ b3)
{
    const int bj = blockIdx.x;
    const int b = bj / NN, j = bj % NN;
    const int tid = threadIdx.x;

    __shared__ float xb[NN*17];            // 6528 B
    __shared__ float W1s[51*H0];           // 10200 B  (all 51 rows of W1)
    __shared__ float W2s[33*H1];           // 6600 B   (rows 0..32)
    __shared__ float W3s[DD*OUTD];         // 4096 B   (rows 0..15)
    __shared__ float b1s[H0], b2s[H1], b3s[OUTD];
    __shared__ float adjrow[NN];
    __shared__ float disrow[NN];
    __shared__ float s[DD];
    __shared__ float red[2];

    // ---- Phase 1: front-batched loads (all independent) ----
    {
        const float4* xB4 = (const float4*)(x + b*NN*DD);
        #pragma unroll
        for (int idx = tid; idx < NN*DD/4; idx += 128) {
            float4 v = xB4[idx];
            const int base = (idx >> 2)*17 + (idx & 3)*4;
            xb[base+0] = v.x; xb[base+1] = v.y; xb[base+2] = v.z; xb[base+3] = v.w;
        }
        const float2* W1v = (const float2*)W1;
        #pragma unroll
        for (int idx = tid; idx < 51*H0/2; idx += 128)
            ((float2*)W1s)[idx] = W1v[idx];
        const float2* W2v = (const float2*)W2;
        #pragma unroll
        for (int idx = tid; idx < 33*H1/2; idx += 128)
            ((float2*)W2s)[idx] = W2v[idx];
        const float4* W3v = (const float4*)W3;
        #pragma unroll
        for (int idx = tid; idx < DD*OUTD/4; idx += 128)
            ((float4*)W3s)[idx] = W3v[idx];
        if (tid < NN)   adjrow[tid] = adj[(b*NN + j)*NN + tid];
        if (tid < H0)   b1s[tid] = b1[tid];
        if (tid < H1)   b2s[tid] = b2[tid];
        if (tid < OUTD) b3s[tid] = b3[tid];
    }
    __syncthreads();

    // ---- Phase 2: dis row j ----
    if (tid < NN) {
        float d2 = 1e-10f;
        #pragma unroll
        for (int d = 0; d < DD; d++) {
            const float df = xb[j*17 + d] - xb[tid*17 + d];
            d2 += df * df;
        }
        disrow[tid] = sqrtf(d2);
    }
    __syncthreads();

    // ---- Phase 3: reductions + g_xw3 (parallel across warps) ----
    if (tid < 32) {
        float dg = 0.f, sd = 0.f;
        #pragma unroll
        for (int k = tid; k < NN; k += 32) {
            const float a = adjrow[k];
            dg += a; sd += a * disrow[k];
        }
        #pragma unroll
        for (int o = 16; o; o >>= 1) {
            dg += __shfl_down_sync(0xffffffffu, dg, o);
            sd += __shfl_down_sync(0xffffffffu, sd, o);
        }
        if (tid == 0) { red[0] = dg; red[1] = sd; g_deg[bj] = dg; }
    }
    if (tid >= 32 && tid < 32 + DD) {
        const int d = tid - 32;
        float acc = 0.f;
        #pragma unroll 4
        for (int k = 0; k < NN; k++) acc += adjrow[k] * xb[k*17 + d];
        s[d] = acc;
    }
    if (tid >= 64) {     // g_xw3[o] = b3 + x_j . W3[0:16,:]
        const int o = tid - 64;
        float acc = b3s[o];
        #pragma unroll
        for (int d = 0; d < DD; d++) acc += xb[j*17 + d] * W3s[d*OUTD + o];
        g_xw3[bj*OUTD + o] = acc;
    }
    __syncthreads();

    // ---- Phase 4: A/P and g_base (smem only) ----
    if (tid < H0) {
        const int h = tid;
        float Av = 0.f, Bv = 0.f, Cv = 0.f;
        #pragma unroll
        for (int d = 0; d < DD; d++) {
            const float xv = xb[j*17 + d];
            Av += xv   * W1s[d*H0 + h];
            Bv += xv   * W1s[(DD + d)*H0 + h];
            Cv += s[d] * W1s[(2*DD + d)*H0 + h];
        }
        g_A[bj*H0 + h] = Av;
        g_P[bj*H0 + h] = red[0]*(Bv + b1s[h]) + Cv + red[1] * W1s[(3*DD + 1)*H0 + h];
    } else if (tid >= 64 && tid < 64 + H1) {
        const int h1 = tid - 64;
        const float dg = red[0];
        float acc = dg * b2s[h1];
        #pragma unroll
        for (int d = 0; d < DD; d++) {
            acc += dg * xb[j*17 + d] * W2s[d*H1 + h1];
            acc += s[d]              * W2s[(DD + d)*H1 + h1];
        }
        acc += red[1] * W2s[(2*DD)*H1 + h1];
        g_base[bj*H1 + h1] = acc;
    }
}

// ---------------------------------------------------------------------------
// Kernel 2: per-(b,i) message + output. grid = B*N, 128 threads.
// ---------------------------------------------------------------------------
__global__ void __launch_bounds__(128) sgc_k2(
    const float* __restrict__ x, const float* __restrict__ adj,
    const float* __restrict__ W1,
    const float* __restrict__ W2,
    const float* __restrict__ W3,
    float* __restrict__ out)
{
    const int bi = blockIdx.x;
    const int b = bi / NN, i = bi % NN;
    const int tid = threadIdx.x;

    __shared__ float xb[NN*17];          // 6528 B
    __shared__ float W2s[H0*H1];         // 10000 B (rows 33..82 of W2)
    __shared__ float W3s[H1*OUTD];       // 12800 B (rows 16..65 of W3)
    __shared__ float Pst[CHUNK*H0];      // 4800 B
    __shared__ float dis_i[NN];
    __shared__ float sdik[NN];
    __shared__ float ddeg[NN];
    __shared__ float ddij[NN];
    __shared__ float A_i[H0], tacc[H0], m2s[H1];
    __shared__ float base2[H1], xw3[OUTD];
    __shared__ float wijS[H0], wikS[H0];
    __shared__ int   nz[NN];
    __shared__ int   wcnt[3];
    __shared__ int   nnzS;

    // ---- Phase A: front-batched loads (all independent) ----
    {
        const float4* xB4 = (const float4*)(x + b*NN*DD);
        #pragma unroll
        for (int idx = tid; idx < NN*DD/4; idx += 128) {
            float4 v = xB4[idx];
            const int base = (idx >> 2)*17 + (idx & 3)*4;
            xb[base+0] = v.x; xb[base+1] = v.y; xb[base+2] = v.z; xb[base+3] = v.w;
        }
        const float2* W2v = (const float2*)(W2 + (2*DD + 1)*H1);   // offset 1650 (8B-aligned)
        #pragma unroll
        for (int idx = tid; idx < H0*H1/2; idx += 128)
            ((float2*)W2s)[idx] = W2v[idx];
        const float4* W3v = (const float4*)(W3 + DD*OUTD);          // offset 1024 (16B-aligned)
        #pragma unroll
        for (int idx = tid; idx < H1*OUTD/4; idx += 128)
            ((float4*)W3s)[idx] = W3v[idx];
        if (tid < H0) {
            A_i[tid]   = g_A[bi*H0 + tid];
            base2[tid] = g_base[bi*H1 + tid];
            wijS[tid]  = W1[(3*DD + 0)*H0 + tid];
            wikS[tid]  = W1[(3*DD + 2)*H0 + tid];
        }
        if (tid >= 64) xw3[tid - 64] = g_xw3[bi*OUTD + (tid - 64)];
    }
    float adjv = 0.f;
    if (tid < NN) adjv = adj[(b*NN + i)*NN + tid];
    __syncthreads();

    // ---- Phase B: dis_i + nonzero compaction ----
    bool nzb = false; unsigned mk = 0u;
    if (tid < NN) {
        float d2 = 1e-10f;
        #pragma unroll
        for (int d = 0; d < DD; d++) {
            const float df = xb[i*17 + d] - xb[tid*17 + d];
            d2 += df * df;
        }
        dis_i[tid] = sqrtf(d2);
        nzb = (adjv != 0.f);
        mk = __ballot_sync(0xffffffffu, nzb);
        if ((tid & 31) == 0) wcnt[tid >> 5] = __popc(mk);
    }
    __syncthreads();
    if (tid < NN && nzb) {
        const int w = tid >> 5, lane = tid & 31;
        int off = __popc(mk & ((1u << lane) - 1u));
        #pragma unroll
        for (int u = 0; u < 3; u++) if (u < w) off += wcnt[u];
        nz[off] = tid;
    }
    if (tid == 0) nnzS = wcnt[0] + wcnt[1] + wcnt[2];
    __syncthreads();

    const int nnz = nnzS;

    // ---- Phase C: per-m scalars + sd_ik (address-dependent load epoch) ----
    if (tid < nnz) {
        const float dg = g_deg[b*NN + nz[tid]];
        ddeg[tid] = dg;
        ddij[tid] = dg * dis_i[nz[tid]];
    }
    {
        const int w = tid >> 5, lane = tid & 31;
        for (int m = w; m < nnz; m += 4) {
            const float* row = adj + (b*NN + nz[m])*NN;
            float v = row[lane]    * dis_i[lane]
                    + row[lane+32] * dis_i[lane+32]
                    + row[lane+64] * dis_i[lane+64];
            #pragma unroll
            for (int o = 16; o; o >>= 1) v += __shfl_down_sync(0xffffffffu, v, o);
            if (lane == 0) sdik[m] = v;
        }
    }
    __syncthreads();

    // ---- Phase D: t[h] = sum over nz j of leaky(S), chunked P staging ----
    float accD = 0.f;
    for (int c0 = 0; c0 < nnz; c0 += CHUNK) {
        const int cn = min(nnz - c0, CHUNK);
        for (int idx = tid; idx < cn*(H0/2); idx += 128) {
            const int m = idx / (H0/2), q = idx % (H0/2);
            ((float2*)Pst)[m*(H0/2) + q] =
                ((const float2*)(g_P + (b*NN + nz[c0+m])*H0))[q];
        }
        __syncthreads();
        if (tid < H0) {
            const float Ah = A_i[tid], wij = wijS[tid], wik = wikS[tid];
            #pragma unroll 4
            for (int m = 0; m < cn; m++) {
                const float Sv = fmaf(ddeg[c0+m], Ah,
                                 fmaf(ddij[c0+m], wij,
                                 fmaf(sdik[c0+m], wik, Pst[m*H0 + tid])));
                accD += leaky(Sv);
            }
        }
        __syncthreads();
    }
    if (tid < H0) tacc[tid] = accD;
    __syncthreads();

    // ---- Phase E: m2_sum = leaky(base2 + t . W2d)  (smem only) ----
    if (tid < H1) {
        float acc = base2[tid];
        #pragma unroll 10
        for (int h = 0; h < H0; h++)
            acc += tacc[h] * W2s[h*H1 + tid];
        m2s[tid] = leaky(acc);
    }
    __syncthreads();

    // ---- Phase F: out = leaky(xw3 + m2s . W3b)  (smem only) ----
    if (tid < OUTD) {
        float acc = xw3[tid];
        #pragma unroll 10
        for (int h = 0; h < H1; h++)
            acc += m2s[h] * W3s[h*OUTD + tid];
        out[bi*OUTD + tid] = leaky(acc);
    }
}

extern "C" void kernel_launch(void* const* d_in, const int* in_sizes, int n_in,
                              void* d_out, int out_size)
{
    const float* x   = (const float*)d_in[0];
    const float* adj = (const float*)d_in[1];
    const float* W1  = (const float*)d_in[2];
    const float* b1  = (const float*)d_in[3];
    const float* W2  = (const float*)d_in[4];
    const float* b2  = (const float*)d_in[5];
    const float* W3  = (const float*)d_in[6];
    const float* b3  = (const float*)d_in[7];
    float* out = (float*)d_out;

    sgc_k1<<<BB*NN, 128>>>(x, adj, W1, b1, W2, b2, W3, b3);
    sgc_k2<<<BB*NN, 128>>>(x, adj, W1, W2, W3, out);
}